// round 16
// baseline (speedup 1.0000x reference)
#include <cuda_runtime.h>
#include <math.h>
#include <stdint.h>

#define BATCH  8
#define SEQ    2048
#define MTOT   (BATCH*SEQ)      // 16384
#define DIN    64
#define HID    256
#define DMODEL 512
#define DINNER 1024
#define DSTATE 16
#define DTRANK 32
#define DCONV  4
#define DOUTD  64

// ---------------- scratch (allocation-free, __device__ globals) ----------------
__device__ float g_h    [MTOT*HID];
__device__ float g_u    [MTOT*DMODEL];
__device__ float g_xz   [MTOT*2*DINNER];   // (xm | z)
__device__ float g_xm   [MTOT*DINNER];
__device__ float g_dbl  [MTOT*64];         // [dt(32)|B(16)|C(16)]
__device__ float g_delta[MTOT*DINNER];
__device__ float g_y    [MTOT*DINNER];     // scan+gate out
__device__ float g_o1   [MTOT*DMODEL];
__device__ float g_h2   [MTOT*HID];

enum Act { ACT_NONE = 0, ACT_RELU = 1, ACT_SOFTPLUS = 2 };

// ---------------- helpers ----------------
__device__ __forceinline__ float to_tf32(float x) {
    float r;
    asm("cvt.rna.tf32.f32 %0, %1;" : "=f"(r) : "f"(x));
    return r;
}

__device__ __forceinline__ void mma8(float c[4], const uint32_t a[4], const uint32_t b[2]) {
    asm volatile(
        "mma.sync.aligned.m16n8k8.row.col.f32.tf32.tf32.f32 "
        "{%0,%1,%2,%3}, {%4,%5,%6,%7}, {%8,%9}, {%0,%1,%2,%3};\n"
        : "+f"(c[0]), "+f"(c[1]), "+f"(c[2]), "+f"(c[3])
        : "r"(a[0]), "r"(a[1]), "r"(a[2]), "r"(a[3]),
          "r"(b[0]), "r"(b[1]));
}

// ---------------- tensor-core GEMM (R2 engine, proven):
// C[M,N] = act(A[M,K(lda)] * W[N,K]^T + bias)
// SPLIT=0: plain tf32.  SPLIT=1: tf32x3 (hi/lo split, fp32-class accuracy).
template<int BM,int BN,int WARPS_M,int WARPS_N,int ACT,int SPLIT>
__global__ void __launch_bounds__(WARPS_M*WARPS_N*32)
gemm_tc(const float* __restrict__ A, const float* __restrict__ W,
        const float* __restrict__ bias, float* __restrict__ C,
        int M, int N, int K, int lda)
{
    constexpr int BK = 32, SK = BK + 4;
    constexpr int THREADS = WARPS_M*WARPS_N*32;
    constexpr int WM = BM/WARPS_M, WN = BN/WARPS_N;
    constexpr int MM = WM/16, MN = WN/8;
    constexpr int NBUF = SPLIT ? 2 : 1;

    extern __shared__ float sm[];
    float* sAh = sm;
    float* sAl = sAh + BM*SK;              // only used if SPLIT
    float* sBh = sm + NBUF*BM*SK;
    float* sBl = sBh + BN*SK;              // only used if SPLIT

    const int tid  = threadIdx.x;
    const int lane = tid & 31;
    const int warp = tid >> 5;
    const int g    = lane >> 2;            // groupID 0..7
    const int c4   = lane & 3;             // threadID_in_group 0..3
    const int wrow = (warp / WARPS_N) * WM;
    const int wcol = (warp % WARPS_N) * WN;
    const int bm   = blockIdx.y * BM;
    const int bn   = blockIdx.x * BN;

    float acc[MM][MN][4];
#pragma unroll
    for (int i = 0; i < MM; i++)
#pragma unroll
        for (int j = 0; j < MN; j++)
#pragma unroll
            for (int q = 0; q < 4; q++) acc[i][j][q] = 0.f;

    for (int k0 = 0; k0 < K; k0 += BK) {
        // load + convert A tile (BM x BK)
        for (int i = tid; i < BM*(BK/4); i += THREADS) {
            int m  = i / (BK/4);
            int kc = (i % (BK/4)) * 4;
            float4 v = *(const float4*)(A + (size_t)(bm + m)*lda + k0 + kc);
            float4 h = make_float4(to_tf32(v.x), to_tf32(v.y), to_tf32(v.z), to_tf32(v.w));
            *(float4*)(sAh + m*SK + kc) = h;
            if (SPLIT) {
                float4 l = make_float4(to_tf32(v.x - h.x), to_tf32(v.y - h.y),
                                       to_tf32(v.z - h.z), to_tf32(v.w - h.w));
                *(float4*)(sAl + m*SK + kc) = l;
            }
        }
        // load + convert W tile (BN x BK)
        for (int i = tid; i < BN*(BK/4); i += THREADS) {
            int n  = i / (BK/4);
            int kc = (i % (BK/4)) * 4;
            float4 v = *(const float4*)(W + (size_t)(bn + n)*K + k0 + kc);
            float4 h = make_float4(to_tf32(v.x), to_tf32(v.y), to_tf32(v.z), to_tf32(v.w));
            *(float4*)(sBh + n*SK + kc) = h;
            if (SPLIT) {
                float4 l = make_float4(to_tf32(v.x - h.x), to_tf32(v.y - h.y),
                                       to_tf32(v.z - h.z), to_tf32(v.w - h.w));
                *(float4*)(sBl + n*SK + kc) = l;
            }
        }
        __syncthreads();

#pragma unroll
        for (int kk = 0; kk < BK; kk += 8) {
            uint32_t ah[MM][4], al[MM][4];
#pragma unroll
            for (int mi = 0; mi < MM; mi++) {
                const float* p = sAh + (wrow + mi*16 + g)*SK + kk + c4;
                ah[mi][0] = __float_as_uint(p[0]);
                ah[mi][1] = __float_as_uint(p[8*SK]);
                ah[mi][2] = __float_as_uint(p[4]);
                ah[mi][3] = __float_as_uint(p[8*SK + 4]);
                if (SPLIT) {
                    const float* q = sAl + (wrow + mi*16 + g)*SK + kk + c4;
                    al[mi][0] = __float_as_uint(q[0]);
                    al[mi][1] = __float_as_uint(q[8*SK]);
                    al[mi][2] = __float_as_uint(q[4]);
                    al[mi][3] = __float_as_uint(q[8*SK + 4]);
                }
            }
#pragma unroll
            for (int ni = 0; ni < MN; ni++) {
                const float* p = sBh + (wcol + ni*8 + g)*SK + kk + c4;
                uint32_t bh[2] = { __float_as_uint(p[0]), __float_as_uint(p[4]) };
                uint32_t bl[2];
                if (SPLIT) {
                    const float* q = sBl + (wcol + ni*8 + g)*SK + kk + c4;
                    bl[0] = __float_as_uint(q[0]);
                    bl[1] = __float_as_uint(q[4]);
                }
#pragma unroll
                for (int mi = 0; mi < MM; mi++) {
                    if (SPLIT) {
                        mma8(acc[mi][ni], al[mi], bh);
                        mma8(acc[mi][ni], ah[mi], bl);
                    }
                    mma8(acc[mi][ni], ah[mi], bh);
                }
            }
        }
        __syncthreads();
    }

    // epilogue
#pragma unroll
    for (int mi = 0; mi < MM; mi++) {
        int r0 = bm + wrow + mi*16 + g;
#pragma unroll
        for (int ni = 0; ni < MN; ni++) {
            int col = bn + wcol + ni*8 + 2*c4;
            float b0 = 0.f, b1 = 0.f;
            if (bias) { b0 = bias[col]; b1 = bias[col + 1]; }
            float v0 = acc[mi][ni][0] + b0;
            float v1 = acc[mi][ni][1] + b1;
            float v2 = acc[mi][ni][2] + b0;
            float v3 = acc[mi][ni][3] + b1;
            if (ACT == ACT_RELU) {
                v0 = fmaxf(v0, 0.f); v1 = fmaxf(v1, 0.f);
                v2 = fmaxf(v2, 0.f); v3 = fmaxf(v3, 0.f);
            }
            if (ACT == ACT_SOFTPLUS) {
                v0 = (v0 > 20.f) ? v0 : log1pf(__expf(v0));
                v1 = (v1 > 20.f) ? v1 : log1pf(__expf(v1));
                v2 = (v2 > 20.f) ? v2 : log1pf(__expf(v2));
                v3 = (v3 > 20.f) ? v3 : log1pf(__expf(v3));
            }
            *(float2*)(C + (size_t)r0*N + col)       = make_float2(v0, v1);
            *(float2*)(C + (size_t)(r0 + 8)*N + col) = make_float2(v2, v3);
        }
    }
}

// ---------------- depthwise causal conv1d (k=4) + bias + SiLU ----------------
__global__ void conv_silu_kernel(const float* __restrict__ conv_w,
                                 const float* __restrict__ conv_b)
{
    int idx = blockIdx.x * blockDim.x + threadIdx.x;
    if (idx >= MTOT * DINNER) return;
    int d  = idx % DINNER;
    int bt = idx / DINNER;
    int t  = bt % SEQ;
    int b  = bt / SEQ;

    float acc = conv_b[d];
#pragma unroll
    for (int j = 0; j < DCONV; j++) {
        int tt = t - (DCONV - 1) + j;
        if (tt >= 0)
            acc = fmaf(conv_w[d*DCONV + j],
                       g_xz[(size_t)(b*SEQ + tt)*(2*DINNER) + d], acc);
    }
    float sv = acc / (1.f + __expf(-acc));     // silu
    g_xm[(size_t)bt*DINNER + d] = sv;
}

// ---------------- selective scan + fused gating ----------------
__global__ void scan_kernel(const float* __restrict__ A_log,
                            const float* __restrict__ D_param)
{
    int gid = blockIdx.x * blockDim.x + threadIdx.x;
    int grp = gid >> 4;          // (b,d)
    int s   = gid & 15;
    if (grp >= BATCH * DINNER) return;
    int b = grp / DINNER;
    int d = grp % DINNER;

    const float Av = -__expf(A_log[d*DSTATE + s]);
    const float Dv = D_param[d];
    const float* drow = g_delta + (size_t)b*SEQ*DINNER + d;
    const float* xrow = g_xm    + (size_t)b*SEQ*DINNER + d;
    const float* zrow = g_xz    + (size_t)b*SEQ*(2*DINNER) + DINNER + d;
    const float* dblb = g_dbl   + (size_t)b*SEQ*64;
    float*       yrow = g_y     + (size_t)b*SEQ*DINNER + d;

    float h = 0.f;
    for (int t = 0; t < SEQ; t++) {
        float dt = drow[(size_t)t*DINNER];
        float xt = xrow[(size_t)t*DINNER];
        float Bt = dblb[t*64 + DTRANK + s];
        float Ct = dblb[t*64 + DTRANK + DSTATE + s];
        float dA = __expf(dt * Av);
        h = fmaf(dA, h, dt * xt * Bt);
        float p = h * Ct;
        p += __shfl_xor_sync(0xffffffffu, p, 8, 16);
        p += __shfl_xor_sync(0xffffffffu, p, 4, 16);
        p += __shfl_xor_sync(0xffffffffu, p, 2, 16);
        p += __shfl_xor_sync(0xffffffffu, p, 1, 16);
        if (s == 0) {
            float z  = zrow[(size_t)t*2*DINNER];
            float yv = p + xt * Dv;
            yrow[(size_t)t*DINNER] = yv * (z / (1.f + __expf(-z)));
        }
    }
}

// ---------------- host launch ----------------
static float* sym_addr(const void* symbol)
{
    void* p = nullptr;
    cudaGetSymbolAddress(&p, symbol);
    return (float*)p;
}

extern "C" void kernel_launch(void* const* d_in, const int* in_sizes, int n_in,
                              void* d_out, int out_size)
{
    const float* x         = (const float*)d_in[0];
    const float* enc_w1    = (const float*)d_in[1];
    const float* enc_b1    = (const float*)d_in[2];
    const float* enc_w2    = (const float*)d_in[3];
    const float* enc_b2    = (const float*)d_in[4];
    const float* in_proj_w = (const float*)d_in[5];
    const float* conv_w    = (const float*)d_in[6];
    const float* conv_b    = (const float*)d_in[7];
    const float* x_proj_w  = (const float*)d_in[8];
    const float* dt_proj_w = (const float*)d_in[9];
    const float* dt_proj_b = (const float*)d_in[10];
    const float* A_log     = (const float*)d_in[11];
    const float* D_param   = (const float*)d_in[12];
    const float* out_proj_w= (const float*)d_in[13];
    const float* dec_w1    = (const float*)d_in[14];
    const float* dec_b1    = (const float*)d_in[15];
    const float* dec_w2    = (const float*)d_in[16];
    const float* dec_b2    = (const float*)d_in[17];
    float* out = (float*)d_out;

    float* ph    = sym_addr(g_h);
    float* pu    = sym_addr(g_u);
    float* pxz   = sym_addr(g_xz);
    float* pxm   = sym_addr(g_xm);
    float* pdbl  = sym_addr(g_dbl);
    float* pdel  = sym_addr(g_delta);
    float* py    = sym_addr(g_y);
    float* po1   = sym_addr(g_o1);
    float* ph2   = sym_addr(g_h2);

    // dynamic smem sizes: (hi[,lo]) for A (BM rows) + B (BN rows), stride 36 floats
    const int SMEM_PLAIN_BIG   = (128 + 128) * 36 * 4;       // 36864
    const int SMEM_SPLIT_BIG   = 2 * (128 + 128) * 36 * 4;   // 73728
    const int SMEM_SPLIT_NARR  = 2 * (128 + 64) * 36 * 4;    // 55296

    cudaFuncSetAttribute(gemm_tc<128,128,2,4,ACT_RELU,1>,
                         cudaFuncAttributeMaxDynamicSharedMemorySize, SMEM_SPLIT_BIG);
    cudaFuncSetAttribute(gemm_tc<128,128,2,4,ACT_SOFTPLUS,1>,
                         cudaFuncAttributeMaxDynamicSharedMemorySize, SMEM_SPLIT_BIG);
    cudaFuncSetAttribute(gemm_tc<128,64,4,2,ACT_NONE,1>,
                         cudaFuncAttributeMaxDynamicSharedMemorySize, SMEM_SPLIT_NARR);
    cudaFuncSetAttribute(gemm_tc<128,128,2,4,ACT_NONE,0>,
                         cudaFuncAttributeMaxDynamicSharedMemorySize, SMEM_PLAIN_BIG);
    cudaFuncSetAttribute(gemm_tc<128,128,2,4,ACT_RELU,0>,
                         cudaFuncAttributeMaxDynamicSharedMemorySize, SMEM_PLAIN_BIG);

    // 1. enc1: relu(x @ enc_w1^T + b1)   [16384,256] K=64   (tf32x3 split)
    gemm_tc<128,128,2,4,ACT_RELU,1><<<dim3(HID/128, MTOT/128), 256, SMEM_SPLIT_BIG>>>(
        x, enc_w1, enc_b1, ph, MTOT, HID, DIN, DIN);

    // 2. enc2: u = h @ enc_w2^T + b2     [16384,512] K=256  (plain tf32)
    gemm_tc<128,128,2,4,ACT_NONE,0><<<dim3(DMODEL/128, MTOT/128), 256, SMEM_PLAIN_BIG>>>(
        ph, enc_w2, enc_b2, pu, MTOT, DMODEL, HID, HID);

    // 3. in_proj: xz = u @ in_proj_w^T   [16384,2048] K=512 (plain tf32)
    gemm_tc<128,128,2,4,ACT_NONE,0><<<dim3(2*DINNER/128, MTOT/128), 256, SMEM_PLAIN_BIG>>>(
        pu, in_proj_w, nullptr, pxz, MTOT, 2*DINNER, DMODEL, DMODEL);

    // 4. conv + bias + silu -> g_xm
    conv_silu_kernel<<<(MTOT*DINNER)/256, 256>>>(conv_w, conv_b);

    // 5. x_proj: dbl = xm @ x_proj_w^T   [16384,64] K=1024  (tf32x3 split)
    gemm_tc<128,64,4,2,ACT_NONE,1><<<dim3(1, MTOT/128), 256, SMEM_SPLIT_NARR>>>(
        pxm, x_proj_w, nullptr, pdbl, MTOT, 64, DINNER, DINNER);

    // 6. dt_proj + softplus: delta       [16384,1024] K=32, lda=64 (tf32x3 split)
    gemm_tc<128,128,2,4,ACT_SOFTPLUS,1><<<dim3(DINNER/128, MTOT/128), 256, SMEM_SPLIT_BIG>>>(
        pdbl, dt_proj_w, dt_proj_b, pdel, MTOT, DINNER, DTRANK, 64);

    // 7. selective scan + fused gating -> g_y
    scan_kernel<<<(BATCH*DINNER*DSTATE)/256, 256>>>(A_log, D_param);

    // 8. out_proj: o1 = y @ out_proj_w^T [16384,512] K=1024 (plain tf32)
    gemm_tc<128,128,2,4,ACT_NONE,0><<<dim3(DMODEL/128, MTOT/128), 256, SMEM_PLAIN_BIG>>>(
        py, out_proj_w, nullptr, po1, MTOT, DMODEL, DINNER, DINNER);

    // 9. dec1: relu                      [16384,256] K=512  (plain tf32)
    gemm_tc<128,128,2,4,ACT_RELU,0><<<dim3(HID/128, MTOT/128), 256, SMEM_PLAIN_BIG>>>(
        po1, dec_w1, dec_b1, ph2, MTOT, HID, DMODEL, DMODEL);

    // 10. dec2 -> out                    [16384,64] K=256   (tf32x3 split)
    gemm_tc<128,64,4,2,ACT_NONE,1><<<dim3(1, MTOT/128), 256, SMEM_SPLIT_NARR>>>(
        ph2, dec_w2, dec_b2, out, MTOT, DOUTD, HID, HID);
}

// round 17
// speedup vs baseline: 1.0067x; 1.0067x over previous
#include <cuda_runtime.h>
#include <math.h>
#include <stdint.h>

#define BATCH  8
#define SEQ    2048
#define MTOT   (BATCH*SEQ)      // 16384
#define DIN    64
#define HID    256
#define DMODEL 512
#define DINNER 1024
#define DSTATE 16
#define DTRANK 32
#define DCONV  4
#define DOUTD  64

// ---------------- scratch (allocation-free, __device__ globals) ----------------
__device__ float g_h    [MTOT*HID];
__device__ float g_u    [MTOT*DMODEL];
__device__ float g_xz   [MTOT*2*DINNER];   // (xm | z)
__device__ float g_xm   [MTOT*DINNER];
__device__ float g_dbl  [MTOT*64];         // [dt(32)|B(16)|C(16)]
__device__ float g_delta[MTOT*DINNER];
__device__ float g_y    [MTOT*DINNER];     // scan+gate out
__device__ float g_o1   [MTOT*DMODEL];
__device__ float g_h2   [MTOT*HID];

enum Act { ACT_NONE = 0, ACT_RELU = 1, ACT_SOFTPLUS = 2 };

// ---------------- helpers ----------------
__device__ __forceinline__ float to_tf32(float x) {
    float r;
    asm("cvt.rna.tf32.f32 %0, %1;" : "=f"(r) : "f"(x));
    return r;
}

__device__ __forceinline__ void mma8(float c[4], const uint32_t a[4], const uint32_t b[2]) {
    asm volatile(
        "mma.sync.aligned.m16n8k8.row.col.f32.tf32.tf32.f32 "
        "{%0,%1,%2,%3}, {%4,%5,%6,%7}, {%8,%9}, {%0,%1,%2,%3};\n"
        : "+f"(c[0]), "+f"(c[1]), "+f"(c[2]), "+f"(c[3])
        : "r"(a[0]), "r"(a[1]), "r"(a[2]), "r"(a[3]),
          "r"(b[0]), "r"(b[1]));
}

// ---------------- tensor-core GEMM with fragment-permuted smem ----------------
// C[M,N] = act(A[M,K(lda)] * W[N,K]^T + bias)
// SPLIT=0: plain tf32.  SPLIT=1: tf32x3 (hi/lo split).
// Smem layout is permuted at fill time so each thread's MMA fragment is ONE
// vector load: A -> float4 per lane per (mtile,ktile); B -> float2 per lane.
template<int BM,int BN,int WARPS_M,int WARPS_N,int ACT,int SPLIT>
__global__ void __launch_bounds__(WARPS_M*WARPS_N*32)
gemm_tc(const float* __restrict__ A, const float* __restrict__ W,
        const float* __restrict__ bias, float* __restrict__ C,
        int M, int N, int K, int lda)
{
    constexpr int BK = 32, KT8 = BK/8;
    constexpr int THREADS = WARPS_M*WARPS_N*32;
    constexpr int WM = BM/WARPS_M, WN = BN/WARPS_N;
    constexpr int MM = WM/16, MN = WN/8;
    constexpr int NBUF = SPLIT ? 2 : 1;
    constexpr int A_FLOATS = BM*BK;   // (BM/16)*KT8*32*4
    constexpr int B_FLOATS = BN*BK;   // (BN/8)*KT8*32*2

    extern __shared__ float sm[];
    float* sAh = sm;
    float* sAl = sAh + A_FLOATS;              // if SPLIT
    float* sBh = sm + NBUF*A_FLOATS;
    float* sBl = sBh + B_FLOATS;              // if SPLIT

    const int tid  = threadIdx.x;
    const int lane = tid & 31;
    const int warp = tid >> 5;
    const int g    = lane >> 2;
    const int c4   = lane & 3;
    const int wrow = (warp / WARPS_N) * WM;
    const int wcol = (warp % WARPS_N) * WN;
    const int amt0 = wrow >> 4;               // first A mtile for this warp
    const int bnt0 = wcol >> 3;               // first B ntile for this warp
    const int bm   = blockIdx.y * BM;
    const int bn   = blockIdx.x * BN;

    float acc[MM][MN][4];
#pragma unroll
    for (int i = 0; i < MM; i++)
#pragma unroll
        for (int j = 0; j < MN; j++)
#pragma unroll
            for (int q = 0; q < 4; q++) acc[i][j][q] = 0.f;

    for (int k0 = 0; k0 < K; k0 += BK) {
        // ---- fill A tile (BM x BK), permuted ----
        for (int i = tid; i < BM*(BK/4); i += THREADS) {
            int m  = i / (BK/4);
            int kc = (i % (BK/4)) * 4;
            float4 v = *(const float4*)(A + (size_t)(bm + m)*lda + k0 + kc);
            float4 h = make_float4(to_tf32(v.x), to_tf32(v.y), to_tf32(v.z), to_tf32(v.w));
            int mt = m >> 4, r = m & 15, gg = r & 7, hb = r >> 3;
            int kt = kc >> 3, ch = (kc >> 2) & 1;
            int comp = hb + 2*ch;
            int base = ((mt*KT8 + kt)*32 + gg*4)*4 + comp;
            sAh[base]      = h.x;
            sAh[base + 4]  = h.y;
            sAh[base + 8]  = h.z;
            sAh[base + 12] = h.w;
            if (SPLIT) {
                sAl[base]      = to_tf32(v.x - h.x);
                sAl[base + 4]  = to_tf32(v.y - h.y);
                sAl[base + 8]  = to_tf32(v.z - h.z);
                sAl[base + 12] = to_tf32(v.w - h.w);
            }
        }
        // ---- fill W tile (BN x BK), permuted ----
        for (int i = tid; i < BN*(BK/4); i += THREADS) {
            int n  = i / (BK/4);
            int kc = (i % (BK/4)) * 4;
            float4 v = *(const float4*)(W + (size_t)(bn + n)*K + k0 + kc);
            float4 h = make_float4(to_tf32(v.x), to_tf32(v.y), to_tf32(v.z), to_tf32(v.w));
            int nt = n >> 3, gg = n & 7;
            int kt = kc >> 3, comp = (kc >> 2) & 1;
            int base = ((nt*KT8 + kt)*32 + gg*4)*2 + comp;
            sBh[base]     = h.x;
            sBh[base + 2] = h.y;
            sBh[base + 4] = h.z;
            sBh[base + 6] = h.w;
            if (SPLIT) {
                sBl[base]     = to_tf32(v.x - h.x);
                sBl[base + 2] = to_tf32(v.y - h.y);
                sBl[base + 4] = to_tf32(v.z - h.z);
                sBl[base + 6] = to_tf32(v.w - h.w);
            }
        }
        __syncthreads();

        const float4* fAh = (const float4*)sAh;
        const float4* fAl = (const float4*)sAl;
        const float2* fBh = (const float2*)sBh;
        const float2* fBl = (const float2*)sBl;

#pragma unroll
        for (int kt = 0; kt < KT8; kt++) {
            uint32_t ah[MM][4], al[MM][4];
#pragma unroll
            for (int mi = 0; mi < MM; mi++) {
                float4 fa = fAh[((amt0 + mi)*KT8 + kt)*32 + lane];
                ah[mi][0] = __float_as_uint(fa.x);
                ah[mi][1] = __float_as_uint(fa.y);
                ah[mi][2] = __float_as_uint(fa.z);
                ah[mi][3] = __float_as_uint(fa.w);
                if (SPLIT) {
                    float4 fl = fAl[((amt0 + mi)*KT8 + kt)*32 + lane];
                    al[mi][0] = __float_as_uint(fl.x);
                    al[mi][1] = __float_as_uint(fl.y);
                    al[mi][2] = __float_as_uint(fl.z);
                    al[mi][3] = __float_as_uint(fl.w);
                }
            }
#pragma unroll
            for (int ni = 0; ni < MN; ni++) {
                float2 fb = fBh[((bnt0 + ni)*KT8 + kt)*32 + lane];
                uint32_t bh[2] = { __float_as_uint(fb.x), __float_as_uint(fb.y) };
                uint32_t bl[2];
                if (SPLIT) {
                    float2 fl = fBl[((bnt0 + ni)*KT8 + kt)*32 + lane];
                    bl[0] = __float_as_uint(fl.x);
                    bl[1] = __float_as_uint(fl.y);
                }
#pragma unroll
                for (int mi = 0; mi < MM; mi++) {
                    if (SPLIT) {
                        mma8(acc[mi][ni], al[mi], bh);
                        mma8(acc[mi][ni], ah[mi], bl);
                    }
                    mma8(acc[mi][ni], ah[mi], bh);
                }
            }
        }
        __syncthreads();
    }

    // ---- epilogue ----
#pragma unroll
    for (int mi = 0; mi < MM; mi++) {
        int r0 = bm + wrow + mi*16 + g;
#pragma unroll
        for (int ni = 0; ni < MN; ni++) {
            int col = bn + wcol + ni*8 + 2*c4;
            float b0 = 0.f, b1 = 0.f;
            if (bias) { b0 = bias[col]; b1 = bias[col + 1]; }
            float v0 = acc[mi][ni][0] + b0;
            float v1 = acc[mi][ni][1] + b1;
            float v2 = acc[mi][ni][2] + b0;
            float v3 = acc[mi][ni][3] + b1;
            if (ACT == ACT_RELU) {
                v0 = fmaxf(v0, 0.f); v1 = fmaxf(v1, 0.f);
                v2 = fmaxf(v2, 0.f); v3 = fmaxf(v3, 0.f);
            }
            if (ACT == ACT_SOFTPLUS) {
                v0 = (v0 > 20.f) ? v0 : log1pf(__expf(v0));
                v1 = (v1 > 20.f) ? v1 : log1pf(__expf(v1));
                v2 = (v2 > 20.f) ? v2 : log1pf(__expf(v2));
                v3 = (v3 > 20.f) ? v3 : log1pf(__expf(v3));
            }
            *(float2*)(C + (size_t)r0*N + col)       = make_float2(v0, v1);
            *(float2*)(C + (size_t)(r0 + 8)*N + col) = make_float2(v2, v3);
        }
    }
}

// ---------------- depthwise causal conv1d (k=4) + bias + SiLU ----------------
__global__ void conv_silu_kernel(const float* __restrict__ conv_w,
                                 const float* __restrict__ conv_b)
{
    int idx = blockIdx.x * blockDim.x + threadIdx.x;
    if (idx >= MTOT * DINNER) return;
    int d  = idx % DINNER;
    int bt = idx / DINNER;
    int t  = bt % SEQ;
    int b  = bt / SEQ;

    float acc = conv_b[d];
#pragma unroll
    for (int j = 0; j < DCONV; j++) {
        int tt = t - (DCONV - 1) + j;
        if (tt >= 0)
            acc = fmaf(conv_w[d*DCONV + j],
                       g_xz[(size_t)(b*SEQ + tt)*(2*DINNER) + d], acc);
    }
    float sv = acc / (1.f + __expf(-acc));     // silu
    g_xm[(size_t)bt*DINNER + d] = sv;
}

// ---------------- selective scan + fused gating ----------------
__global__ void scan_kernel(const float* __restrict__ A_log,
                            const float* __restrict__ D_param)
{
    int gid = blockIdx.x * blockDim.x + threadIdx.x;
    int grp = gid >> 4;          // (b,d)
    int s   = gid & 15;
    if (grp >= BATCH * DINNER) return;
    int b = grp / DINNER;
    int d = grp % DINNER;

    const float Av = -__expf(A_log[d*DSTATE + s]);
    const float Dv = D_param[d];
    const float* drow = g_delta + (size_t)b*SEQ*DINNER + d;
    const float* xrow = g_xm    + (size_t)b*SEQ*DINNER + d;
    const float* zrow = g_xz    + (size_t)b*SEQ*(2*DINNER) + DINNER + d;
    const float* dblb = g_dbl   + (size_t)b*SEQ*64;
    float*       yrow = g_y     + (size_t)b*SEQ*DINNER + d;

    float h = 0.f;
    for (int t = 0; t < SEQ; t++) {
        float dt = drow[(size_t)t*DINNER];
        float xt = xrow[(size_t)t*DINNER];
        float Bt = dblb[t*64 + DTRANK + s];
        float Ct = dblb[t*64 + DTRANK + DSTATE + s];
        float dA = __expf(dt * Av);
        h = fmaf(dA, h, dt * xt * Bt);
        float p = h * Ct;
        p += __shfl_xor_sync(0xffffffffu, p, 8, 16);
        p += __shfl_xor_sync(0xffffffffu, p, 4, 16);
        p += __shfl_xor_sync(0xffffffffu, p, 2, 16);
        p += __shfl_xor_sync(0xffffffffu, p, 1, 16);
        if (s == 0) {
            float z  = zrow[(size_t)t*2*DINNER];
            float yv = p + xt * Dv;
            yrow[(size_t)t*DINNER] = yv * (z / (1.f + __expf(-z)));
        }
    }
}

// ---------------- host launch ----------------
static float* sym_addr(const void* symbol)
{
    void* p = nullptr;
    cudaGetSymbolAddress(&p, symbol);
    return (float*)p;
}

extern "C" void kernel_launch(void* const* d_in, const int* in_sizes, int n_in,
                              void* d_out, int out_size)
{
    const float* x         = (const float*)d_in[0];
    const float* enc_w1    = (const float*)d_in[1];
    const float* enc_b1    = (const float*)d_in[2];
    const float* enc_w2    = (const float*)d_in[3];
    const float* enc_b2    = (const float*)d_in[4];
    const float* in_proj_w = (const float*)d_in[5];
    const float* conv_w    = (const float*)d_in[6];
    const float* conv_b    = (const float*)d_in[7];
    const float* x_proj_w  = (const float*)d_in[8];
    const float* dt_proj_w = (const float*)d_in[9];
    const float* dt_proj_b = (const float*)d_in[10];
    const float* A_log     = (const float*)d_in[11];
    const float* D_param   = (const float*)d_in[12];
    const float* out_proj_w= (const float*)d_in[13];
    const float* dec_w1    = (const float*)d_in[14];
    const float* dec_b1    = (const float*)d_in[15];
    const float* dec_w2    = (const float*)d_in[16];
    const float* dec_b2    = (const float*)d_in[17];
    float* out = (float*)d_out;

    float* ph    = sym_addr(g_h);
    float* pu    = sym_addr(g_u);
    float* pxz   = sym_addr(g_xz);
    float* pxm   = sym_addr(g_xm);
    float* pdbl  = sym_addr(g_dbl);
    float* pdel  = sym_addr(g_delta);
    float* py    = sym_addr(g_y);
    float* po1   = sym_addr(g_o1);
    float* ph2   = sym_addr(g_h2);

    // dynamic smem: permuted tiles, no padding
    const int SMEM_PLAIN_BIG  = (128 + 128) * 32 * 4;       // 32768
    const int SMEM_SPLIT_BIG  = 2 * (128 + 128) * 32 * 4;   // 65536
    const int SMEM_SPLIT_NARR = 2 * (128 + 64) * 32 * 4;    // 49152

    cudaFuncSetAttribute(gemm_tc<128,128,2,4,ACT_RELU,1>,
                         cudaFuncAttributeMaxDynamicSharedMemorySize, SMEM_SPLIT_BIG);
    cudaFuncSetAttribute(gemm_tc<128,128,2,4,ACT_SOFTPLUS,1>,
                         cudaFuncAttributeMaxDynamicSharedMemorySize, SMEM_SPLIT_BIG);
    cudaFuncSetAttribute(gemm_tc<128,64,4,2,ACT_NONE,1>,
                         cudaFuncAttributeMaxDynamicSharedMemorySize, SMEM_SPLIT_NARR);
    cudaFuncSetAttribute(gemm_tc<128,128,2,4,ACT_NONE,0>,
                         cudaFuncAttributeMaxDynamicSharedMemorySize, SMEM_PLAIN_BIG);
    cudaFuncSetAttribute(gemm_tc<128,128,2,4,ACT_RELU,0>,
                         cudaFuncAttributeMaxDynamicSharedMemorySize, SMEM_PLAIN_BIG);

    // 1. enc1: relu(x @ enc_w1^T + b1)   [16384,256] K=64   (tf32x3 split)
    gemm_tc<128,128,2,4,ACT_RELU,1><<<dim3(HID/128, MTOT/128), 256, SMEM_SPLIT_BIG>>>(
        x, enc_w1, enc_b1, ph, MTOT, HID, DIN, DIN);

    // 2. enc2: u = h @ enc_w2^T + b2     [16384,512] K=256  (plain tf32)
    gemm_tc<128,128,2,4,ACT_NONE,0><<<dim3(DMODEL/128, MTOT/128), 256, SMEM_PLAIN_BIG>>>(
        ph, enc_w2, enc_b2, pu, MTOT, DMODEL, HID, HID);

    // 3. in_proj: xz = u @ in_proj_w^T   [16384,2048] K=512 (plain tf32)
    gemm_tc<128,128,2,4,ACT_NONE,0><<<dim3(2*DINNER/128, MTOT/128), 256, SMEM_PLAIN_BIG>>>(
        pu, in_proj_w, nullptr, pxz, MTOT, 2*DINNER, DMODEL, DMODEL);

    // 4. conv + bias + silu -> g_xm
    conv_silu_kernel<<<(MTOT*DINNER)/256, 256>>>(conv_w, conv_b);

    // 5. x_proj: dbl = xm @ x_proj_w^T   [16384,64] K=1024  (tf32x3 split)
    gemm_tc<128,64,4,2,ACT_NONE,1><<<dim3(1, MTOT/128), 256, SMEM_SPLIT_NARR>>>(
        pxm, x_proj_w, nullptr, pdbl, MTOT, 64, DINNER, DINNER);

    // 6. dt_proj + softplus: delta       [16384,1024] K=32, lda=64 (tf32x3 split)
    gemm_tc<128,128,2,4,ACT_SOFTPLUS,1><<<dim3(DINNER/128, MTOT/128), 256, SMEM_SPLIT_BIG>>>(
        pdbl, dt_proj_w, dt_proj_b, pdel, MTOT, DINNER, DTRANK, 64);

    // 7. selective scan + fused gating -> g_y
    scan_kernel<<<(BATCH*DINNER*DSTATE)/256, 256>>>(A_log, D_param);

    // 8. out_proj: o1 = y @ out_proj_w^T [16384,512] K=1024 (plain tf32)
    gemm_tc<128,128,2,4,ACT_NONE,0><<<dim3(DMODEL/128, MTOT/128), 256, SMEM_PLAIN_BIG>>>(
        py, out_proj_w, nullptr, po1, MTOT, DMODEL, DINNER, DINNER);

    // 9. dec1: relu                      [16384,256] K=512  (plain tf32)
    gemm_tc<128,128,2,4,ACT_RELU,0><<<dim3(HID/128, MTOT/128), 256, SMEM_PLAIN_BIG>>>(
        po1, dec_w1, dec_b1, ph2, MTOT, HID, DMODEL, DMODEL);

    // 10. dec2 -> out                    [16384,64] K=256   (tf32x3 split)
    gemm_tc<128,64,4,2,ACT_NONE,1><<<dim3(1, MTOT/128), 256, SMEM_SPLIT_NARR>>>(
        ph2, dec_w2, dec_b2, out, MTOT, DOUTD, HID, HID);
}